// round 10
// baseline (speedup 1.0000x reference)
#include <cuda_runtime.h>
#include <cstdint>
#include <math.h>

// CBOW negative-sampling loss.
//   d_in[0]: in_embed  float32 [100000, 128]
//   d_in[1]: out_embed float32 [100000, 128]
//   d_in[2]: context   int32   [B, 8]
//   d_in[3]: target    int32   [B]
//   d_in[4]: negatives int32   [B, 10]
// Output: float32 [B]
//
// Round 10: cp.async staging + commit-group pipelining + grouped compute.
// 64-thread CTAs; each warp owns TWO elements. All 38 row-copies issued
// back-to-back into smem (4 commit groups: ctxA, uA, ctxB, uB) with zero
// register cost per outstanding load; wait_group 1 releases the mean phase
// while element B's u-rows are still in flight; wait_group 0 releases dots.
// Compute runs in 16-lane groups (group g = element g) reading smem slots
// {sub, sub+16}: 4-stage reduce + 2-lane epilogue (cheap R5 shape) without
// any load-destination register pressure. 38KB smem/CTA -> 5 CTAs/SM ->
// 380 rows (190KB) staged in flight per SM, saturating the per-SM L2
// return path instead of warp-latency exposure.

#define CTX   8
#define NEG   10
#define D     128
#define ROWS  (CTX + 1 + NEG)      // 19
#define WPB   2                    // warps per block, 2 elements each

__device__ __forceinline__ float log_sigmoid_fast(float x) {
    return fminf(x, 0.0f) - __logf(1.0f + __expf(-fabsf(x)));
}

__device__ __forceinline__ float dot4(float4 a, float4 b) {
    return a.x * b.x + a.y * b.y + a.z * b.z + a.w * b.w;
}

__device__ __forceinline__ void cp_async16(unsigned int saddr, const void* gptr) {
    asm volatile("cp.async.cg.shared.global [%0], [%1], 16;"
                 :: "r"(saddr), "l"(gptr) : "memory");
}
__device__ __forceinline__ void cp_commit() {
    asm volatile("cp.async.commit_group;" ::: "memory");
}
template <int N>
__device__ __forceinline__ void cp_wait_group() {
    asm volatile("cp.async.wait_group %0;" :: "n"(N) : "memory");
}

__global__ __launch_bounds__(32 * WPB) void cbow_neg_kernel(
    const float* __restrict__ in_embed,
    const float* __restrict__ out_embed,
    const int*   __restrict__ context,
    const int*   __restrict__ target,
    const int*   __restrict__ negatives,
    float*       __restrict__ out,
    int B)
{
    __shared__ float4 stage[WPB][2][ROWS][32];   // 2*2*19*512B = 38912B

    const int warp = threadIdx.x >> 5;
    const int lane = threadIdx.x & 31;
    const int base = (blockIdx.x * WPB + warp) * 2;   // first of 2 elements
    if (base >= B) return;                            // B % 4 == 0

    // ---- issue ALL 38 row copies, 4 commit groups ----
    // groups in completion order: g0=ctx(e0), g1=u(e0), g2=ctx(e1), g3=u(e1)
    #pragma unroll
    for (int p = 0; p < 2; p++) {
        const int e = base + p;

        #pragma unroll
        for (int c = 0; c < CTX; c++) {
            const int idx = __ldg(&context[e * CTX + c]);
            const float* src = in_embed + (size_t)idx * D + lane * 4;
            unsigned int dst =
                (unsigned int)__cvta_generic_to_shared(&stage[warp][p][c][lane]);
            cp_async16(dst, src);
        }
        cp_commit();                                  // ctx group for element p

        {
            const int t = __ldg(&target[e]);
            const float* src = out_embed + (size_t)t * D + lane * 4;
            unsigned int dst =
                (unsigned int)__cvta_generic_to_shared(&stage[warp][p][CTX][lane]);
            cp_async16(dst, src);
        }
        #pragma unroll
        for (int k = 0; k < NEG; k++) {
            const int idx = __ldg(&negatives[e * NEG + k]);
            const float* src = out_embed + (size_t)idx * D + lane * 4;
            unsigned int dst = (unsigned int)__cvta_generic_to_shared(
                                   &stage[warp][p][CTX + 1 + k][lane]);
            cp_async16(dst, src);
        }
        cp_commit();                                  // u group for element p
    }

    // ---- grouped compute: group g (lanes g*16..g*16+15) = element g ----
    const int group = lane >> 4;
    const int sub   = lane & 15;

    // wait until both ctx groups done (g0..g2 retired; only g3=u(e1) pending)
    cp_wait_group<1>();
    __syncwarp();

    float4 v0 = stage[warp][group][0][sub];
    float4 v1 = stage[warp][group][0][sub + 16];
    #pragma unroll
    for (int c = 1; c < CTX; c++) {
        const float4 a = stage[warp][group][c][sub];
        const float4 b = stage[warp][group][c][sub + 16];
        v0.x += a.x; v0.y += a.y; v0.z += a.z; v0.w += a.w;
        v1.x += b.x; v1.y += b.y; v1.z += b.z; v1.w += b.w;
    }
    const float inv = 1.0f / (float)CTX;
    v0.x *= inv; v0.y *= inv; v0.z *= inv; v0.w *= inv;
    v1.x *= inv; v1.y *= inv; v1.z *= inv; v1.w *= inv;

    // all copies done
    cp_wait_group<0>();
    __syncwarp();

    float s[NEG + 1];
    #pragma unroll
    for (int i = 0; i < NEG + 1; i++) {
        const float4 a = stage[warp][group][CTX + i][sub];
        const float4 b = stage[warp][group][CTX + i][sub + 16];
        s[i] = dot4(v0, a) + dot4(v1, b);
    }

    // ---- reduce within 16-lane group (4 stages) ----
    #pragma unroll
    for (int i = 0; i < NEG + 1; i++) {
        float x = s[i];
        x += __shfl_xor_sync(0xffffffffu, x, 8);
        x += __shfl_xor_sync(0xffffffffu, x, 4);
        x += __shfl_xor_sync(0xffffffffu, x, 2);
        x += __shfl_xor_sync(0xffffffffu, x, 1);
        s[i] = x;
    }

    // ---- epilogue: 2 group leaders per warp ----
    if (sub == 0) {
        float acc = log_sigmoid_fast(s[0]);
        #pragma unroll
        for (int k = 0; k < NEG; k++)
            acc += log_sigmoid_fast(-s[1 + k]);
        out[base + group] = -acc;
    }
}

extern "C" void kernel_launch(void* const* d_in, const int* in_sizes, int n_in,
                              void* d_out, int out_size)
{
    const float* in_embed  = (const float*)d_in[0];
    const float* out_embed = (const float*)d_in[1];
    const int*   context   = (const int*)d_in[2];
    const int*   target    = (const int*)d_in[3];
    const int*   negatives = (const int*)d_in[4];
    float*       out       = (float*)d_out;

    const int B = out_size;                           // 16384
    const int elems_per_block = WPB * 2;              // 4
    const int blocks = (B + elems_per_block - 1) / elems_per_block;   // 4096
    cbow_neg_kernel<<<blocks, 32 * WPB>>>(in_embed, out_embed, context, target,
                                          negatives, out, B);
}

// round 11
// speedup vs baseline: 1.0298x; 1.0298x over previous
#include <cuda_runtime.h>
#include <cstdint>
#include <math.h>

// CBOW negative-sampling loss.
//   d_in[0]: in_embed  float32 [100000, 128]
//   d_in[1]: out_embed float32 [100000, 128]
//   d_in[2]: context   int32   [B, 8]
//   d_in[3]: target    int32   [B]
//   d_in[4]: negatives int32   [B, 10]
// Output: float32 [B]
//
// Round 11: overlap the two gather phases. Per warp (2 elements):
//   1) 19 index loads (L2-resident, broadcast)
//   2) issue 22 cp.async u-row copies into smem (ZERO register cost)
//   3) issue all 16 ctx-row LDGs into registers (critical path to mean)
//   4) mean  -> u copies complete for free underneath ctx+mean
//   5) wait_group 0, dots from smem (16-lane groups), reduce, epilogue
// The per-warp serial memory exposure drops from ctx+u (2 gather
// latencies, R5) to ~1. smem = 4w x 2e x 11rows x 512B = 44KB ->
// 5 CTAs/SM -> 20 warps/SM; regs may float to ~90 (smem caps anyway).

#define CTX   8
#define NEG   10
#define D     128
#define UROWS (NEG + 1)            // 11
#define WPB   4                    // warps per block, 2 elements each

__device__ __forceinline__ float log_sigmoid_fast(float x) {
    return fminf(x, 0.0f) - __logf(1.0f + __expf(-fabsf(x)));
}

__device__ __forceinline__ float dot4(float4 a, float4 b) {
    return a.x * b.x + a.y * b.y + a.z * b.z + a.w * b.w;
}

__device__ __forceinline__ void cp_async16(unsigned int saddr, const void* gptr) {
    asm volatile("cp.async.cg.shared.global [%0], [%1], 16;"
                 :: "r"(saddr), "l"(gptr) : "memory");
}
__device__ __forceinline__ void cp_commit() {
    asm volatile("cp.async.commit_group;" ::: "memory");
}
template <int N>
__device__ __forceinline__ void cp_wait_group() {
    asm volatile("cp.async.wait_group %0;" :: "n"(N) : "memory");
}

__global__ __launch_bounds__(32 * WPB) void cbow_neg_kernel(
    const float* __restrict__ in_embed,
    const float* __restrict__ out_embed,
    const int*   __restrict__ context,
    const int*   __restrict__ target,
    const int*   __restrict__ negatives,
    float*       __restrict__ out,
    int B)
{
    __shared__ float4 stage[WPB][2][UROWS][32];   // 4*2*11*512B = 45056B

    const int warp = threadIdx.x >> 5;
    const int lane = threadIdx.x & 31;
    const int base = (blockIdx.x * WPB + warp) * 2;   // first of 2 elements
    if (base >= B) return;                            // B % 8 == 0

    // ---- 1) all indices up front (warp-uniform, L1/L2 broadcast) ----
    int cidx[2][CTX];
    int uidx[2][UROWS];
    #pragma unroll
    for (int p = 0; p < 2; p++) {
        const int e = base + p;
        #pragma unroll
        for (int c = 0; c < CTX; c++) cidx[p][c] = __ldg(&context[e * CTX + c]);
        uidx[p][0] = __ldg(&target[e]);
        #pragma unroll
        for (int k = 0; k < NEG; k++) uidx[p][1 + k] = __ldg(&negatives[e * NEG + k]);
    }

    // ---- 2) issue all 22 u-row copies (register-free MLP) ----
    #pragma unroll
    for (int p = 0; p < 2; p++) {
        #pragma unroll
        for (int i = 0; i < UROWS; i++) {
            const float* src = out_embed + (size_t)uidx[p][i] * D + lane * 4;
            unsigned int dst = (unsigned int)__cvta_generic_to_shared(
                                   &stage[warp][p][i][lane]);
            cp_async16(dst, src);
        }
    }
    cp_commit();

    // ---- 3+4) ctx rows via LDG, mean; u copies fly underneath ----
    const int group = lane >> 4;          // element within warp
    const int sub   = lane & 15;          // lane within 16-lane group

    float4 v0, v1;
    {
        const float4* r = reinterpret_cast<const float4*>(
                              in_embed + (size_t)cidx[group][0] * D);
        v0 = __ldg(r + sub);
        v1 = __ldg(r + sub + 16);
    }
    #pragma unroll
    for (int c = 1; c < CTX; c++) {
        const float4* r = reinterpret_cast<const float4*>(
                              in_embed + (size_t)cidx[group][c] * D);
        const float4 a = __ldg(r + sub);
        const float4 b = __ldg(r + sub + 16);
        v0.x += a.x; v0.y += a.y; v0.z += a.z; v0.w += a.w;
        v1.x += b.x; v1.y += b.y; v1.z += b.z; v1.w += b.w;
    }
    const float inv = 1.0f / (float)CTX;
    v0.x *= inv; v0.y *= inv; v0.z *= inv; v0.w *= inv;
    v1.x *= inv; v1.y *= inv; v1.z *= inv; v1.w *= inv;

    // ---- 5) dots from smem ----
    cp_wait_group<0>();
    __syncwarp();

    float s[UROWS];
    #pragma unroll
    for (int i = 0; i < UROWS; i++) {
        const float4 a = stage[warp][group][i][sub];
        const float4 b = stage[warp][group][i][sub + 16];
        s[i] = dot4(v0, a) + dot4(v1, b);
    }

    // ---- reduce within 16-lane group (4 stages) ----
    #pragma unroll
    for (int i = 0; i < UROWS; i++) {
        float x = s[i];
        x += __shfl_xor_sync(0xffffffffu, x, 8);
        x += __shfl_xor_sync(0xffffffffu, x, 4);
        x += __shfl_xor_sync(0xffffffffu, x, 2);
        x += __shfl_xor_sync(0xffffffffu, x, 1);
        s[i] = x;
    }

    // ---- epilogue: 2 group leaders per warp ----
    if (sub == 0) {
        float acc = log_sigmoid_fast(s[0]);
        #pragma unroll
        for (int k = 0; k < NEG; k++)
            acc += log_sigmoid_fast(-s[1 + k]);
        out[base + group] = -acc;
    }
}

extern "C" void kernel_launch(void* const* d_in, const int* in_sizes, int n_in,
                              void* d_out, int out_size)
{
    const float* in_embed  = (const float*)d_in[0];
    const float* out_embed = (const float*)d_in[1];
    const int*   context   = (const int*)d_in[2];
    const int*   target    = (const int*)d_in[3];
    const int*   negatives = (const int*)d_in[4];
    float*       out       = (float*)d_out;

    const int B = out_size;                           // 16384
    const int elems_per_block = WPB * 2;              // 8
    const int blocks = (B + elems_per_block - 1) / elems_per_block;   // 2048
    cbow_neg_kernel<<<blocks, 32 * WPB>>>(in_embed, out_embed, context, target,
                                          negatives, out, B);
}

// round 12
// speedup vs baseline: 1.1238x; 1.0913x over previous
#include <cuda_runtime.h>
#include <cstdint>
#include <math.h>

// CBOW negative-sampling loss.
//   d_in[0]: in_embed  float32 [100000, 128]
//   d_in[1]: out_embed float32 [100000, 128]
//   d_in[2]: context   int32   [B, 8]
//   d_in[3]: target    int32   [B]
//   d_in[4]: negatives int32   [B, 10]
// Output: float32 [B]
//
// Round 12: software-pipelined double-buffered gather. Persistent warps
// (grid=740, 64-thr CTAs, 5 CTAs/SM via 38.9KB static smem) grid-stride
// over elements. While computing element i from buffer b, all 19 row
// copies for element i+1 are already in flight into buffer b^1
// (cp.async commit-group per iteration, wait_group<1> = current ready).
// This keeps ~9.7KB of loads in flight per warp ~100% of the time:
// demand ~93 B/cyc/SM vs the ~42 B/cyc/SM LTS share -> memory-system
// bound instead of warp-latency bound.

#define CTX   8
#define NEG   10
#define D     128
#define ROWS  (CTX + 1 + NEG)      // 19
#define WPB   2                    // warps per block (64 threads)

__device__ __forceinline__ float log_sigmoid_fast(float x) {
    return fminf(x, 0.0f) - __logf(1.0f + __expf(-fabsf(x)));
}

__device__ __forceinline__ float dot4(float4 a, float4 b) {
    return a.x * b.x + a.y * b.y + a.z * b.z + a.w * b.w;
}

__device__ __forceinline__ void cp_async16(unsigned int saddr, const void* gptr) {
    asm volatile("cp.async.cg.shared.global [%0], [%1], 16;"
                 :: "r"(saddr), "l"(gptr) : "memory");
}
__device__ __forceinline__ void cp_commit() {
    asm volatile("cp.async.commit_group;" ::: "memory");
}
template <int N>
__device__ __forceinline__ void cp_wait_group() {
    asm volatile("cp.async.wait_group %0;" :: "n"(N) : "memory");
}

// Issue all 19 row copies for element e into stage buffer `buf`.
// Indices loaded vectorized (ctx: 2x int4; negs: 5x int2; tgt: scalar).
__device__ __forceinline__ void prefetch_element(
    float4 (*stage)[ROWS][32],   // [2 bufs][ROWS][32]
    int buf, int e, int lane,
    const float* __restrict__ in_embed,
    const float* __restrict__ out_embed,
    const int*   __restrict__ context,
    const int*   __restrict__ target,
    const int*   __restrict__ negatives)
{
    // ---- indices (warp-uniform, vectorized) ----
    const int4 c0 = __ldg(reinterpret_cast<const int4*>(context + e * CTX));
    const int4 c1 = __ldg(reinterpret_cast<const int4*>(context + e * CTX) + 1);
    const int  tg = __ldg(&target[e]);
    int2 n01 = __ldg(reinterpret_cast<const int2*>(negatives + e * NEG));
    int2 n23 = __ldg(reinterpret_cast<const int2*>(negatives + e * NEG) + 1);
    int2 n45 = __ldg(reinterpret_cast<const int2*>(negatives + e * NEG) + 2);
    int2 n67 = __ldg(reinterpret_cast<const int2*>(negatives + e * NEG) + 3);
    int2 n89 = __ldg(reinterpret_cast<const int2*>(negatives + e * NEG) + 4);

    int idx[ROWS];
    idx[0] = c0.x; idx[1] = c0.y; idx[2] = c0.z; idx[3] = c0.w;
    idx[4] = c1.x; idx[5] = c1.y; idx[6] = c1.z; idx[7] = c1.w;
    idx[8] = tg;
    idx[9]  = n01.x; idx[10] = n01.y; idx[11] = n23.x; idx[12] = n23.y;
    idx[13] = n45.x; idx[14] = n45.y; idx[15] = n67.x; idx[16] = n67.y;
    idx[17] = n89.x; idx[18] = n89.y;

    // ---- 19 async row copies, 16B per lane ----
    #pragma unroll
    for (int r = 0; r < ROWS; r++) {
        const float* table = (r < CTX) ? in_embed : out_embed;
        const float* src = table + (size_t)idx[r] * D + lane * 4;
        unsigned int dst =
            (unsigned int)__cvta_generic_to_shared(&stage[buf][r][lane]);
        cp_async16(dst, src);
    }
}

__device__ __forceinline__ void compute_element(
    float4 (*stage)[ROWS][32], int buf, int e, int lane,
    float* __restrict__ out)
{
    // v = mean of 8 context rows (lane's 16B slot)
    float4 v = stage[buf][0][lane];
    #pragma unroll
    for (int c = 1; c < CTX; c++) {
        const float4 a = stage[buf][c][lane];
        v.x += a.x; v.y += a.y; v.z += a.z; v.w += a.w;
    }
    const float inv = 1.0f / (float)CTX;
    v.x *= inv; v.y *= inv; v.z *= inv; v.w *= inv;

    float s[NEG + 1];
    #pragma unroll
    for (int i = 0; i < NEG + 1; i++)
        s[i] = dot4(v, stage[buf][CTX + i][lane]);

    #pragma unroll
    for (int i = 0; i < NEG + 1; i++) {
        float x = s[i];
        x += __shfl_xor_sync(0xffffffffu, x, 16);
        x += __shfl_xor_sync(0xffffffffu, x, 8);
        x += __shfl_xor_sync(0xffffffffu, x, 4);
        x += __shfl_xor_sync(0xffffffffu, x, 2);
        x += __shfl_xor_sync(0xffffffffu, x, 1);
        s[i] = x;
    }

    if (lane == 0) {
        float acc = log_sigmoid_fast(s[0]);
        #pragma unroll
        for (int k = 0; k < NEG; k++)
            acc += log_sigmoid_fast(-s[1 + k]);
        out[e] = -acc;
    }
}

__global__ __launch_bounds__(32 * WPB) void cbow_neg_kernel(
    const float* __restrict__ in_embed,
    const float* __restrict__ out_embed,
    const int*   __restrict__ context,
    const int*   __restrict__ target,
    const int*   __restrict__ negatives,
    float*       __restrict__ out,
    int B)
{
    __shared__ float4 stage_all[WPB][2][ROWS][32];   // 2w*2b*19*512 = 38912B

    const int warp = threadIdx.x >> 5;
    const int lane = threadIdx.x & 31;
    const int gw   = blockIdx.x * WPB + warp;       // global warp id
    const int TW   = gridDim.x * WPB;               // total warps

    float4 (*stage)[ROWS][32] = stage_all[warp];

    int e = gw;
    if (e >= B) return;

    // prime the pipeline: element e into buffer 0
    prefetch_element(stage, 0, e, lane,
                     in_embed, out_embed, context, target, negatives);
    cp_commit();

    int buf = 0;
    for (; e < B; ) {
        const int nxt = e + TW;
        if (nxt < B)
            prefetch_element(stage, buf ^ 1, nxt, lane,
                             in_embed, out_embed, context, target, negatives);
        cp_commit();                 // one group per iteration (may be empty)

        cp_wait_group<1>();          // current buffer's group is complete
        __syncwarp();

        compute_element(stage, buf, e, lane, out);

        e = nxt;
        buf ^= 1;
    }
}

extern "C" void kernel_launch(void* const* d_in, const int* in_sizes, int n_in,
                              void* d_out, int out_size)
{
    const float* in_embed  = (const float*)d_in[0];
    const float* out_embed = (const float*)d_in[1];
    const int*   context   = (const int*)d_in[2];
    const int*   target    = (const int*)d_in[3];
    const int*   negatives = (const int*)d_in[4];
    float*       out       = (float*)d_out;

    const int B = out_size;                 // 16384
    // persistent-style: 5 CTAs/SM x 148 SMs (smem-capped residency)
    int blocks = 740;
    const int maxBlocks = (B + WPB - 1) / WPB;
    if (blocks > maxBlocks) blocks = maxBlocks;
    cbow_neg_kernel<<<blocks, 32 * WPB>>>(in_embed, out_embed, context, target,
                                          negatives, out, B);
}

// round 13
// speedup vs baseline: 1.2389x; 1.1024x over previous
#include <cuda_runtime.h>
#include <cstdint>
#include <math.h>

// CBOW negative-sampling loss.
//   d_in[0]: in_embed  float32 [100000, 128]
//   d_in[1]: out_embed float32 [100000, 128]
//   d_in[2]: context   int32   [B, 8]
//   d_in[3]: target    int32   [B]
//   d_in[4]: negatives int32   [B, 10]
// Output: float32 [B]
//
// Round 13: R5 structure (best: 18.5us — 2 elements/warp, 16-lane groups,
// 128-thread blocks) + L2 residency protection scoped to out_embed ONLY.
// Evidence: all structures converge to the ~4TB/s DRAM random-512B service
// ceiling in flushed mode; the remaining lever is steady-state L2 residency
// across graph replays. out_embed (51MB, 58% of row touches) fits easily in
// the ~120MB L2, so evict_last on just those loads can actually stick
// (R3 applied it to both tables = 102MB demanded -> inert).

#define CTX 8
#define NEG 10
#define D   128

__device__ __forceinline__ float log_sigmoid_fast(float x) {
    return fminf(x, 0.0f) - __logf(1.0f + __expf(-fabsf(x)));
}

__device__ __forceinline__ float dot4(float4 a, float4 b) {
    return a.x * b.x + a.y * b.y + a.z * b.z + a.w * b.w;
}

// evict_last load for out_embed rows (createpolicy + cache_hint form;
// bare .L2::evict_last on v4.f32 is rejected by this ptxas).
__device__ __forceinline__ float4 ldg_keep(const float4* p) {
    float4 r;
    asm("{\n\t"
        ".reg .b64 pol;\n\t"
        "createpolicy.fractional.L2::evict_last.b64 pol, 1.0;\n\t"
        "ld.global.nc.L2::cache_hint.v4.f32 {%0,%1,%2,%3}, [%4], pol;\n\t"
        "}"
        : "=f"(r.x), "=f"(r.y), "=f"(r.z), "=f"(r.w)
        : "l"(p));
    return r;
}

__global__ __launch_bounds__(128) void cbow_neg_kernel(
    const float* __restrict__ in_embed,
    const float* __restrict__ out_embed,
    const int*   __restrict__ context,
    const int*   __restrict__ target,
    const int*   __restrict__ negatives,
    float*       __restrict__ out,
    int B)
{
    const int lane   = threadIdx.x & 31;
    const int warpId = (blockIdx.x * blockDim.x + threadIdx.x) >> 5;
    const int group  = lane >> 4;            // 0..1: element within warp
    const int sub    = lane & 15;            // 0..15: lane within group
    const int e      = warpId * 2 + group;   // batch element
    if (e >= B) return;                      // B even, warp-uniform exit

    // ---- context indices (vectorized: 2x int4 per element) ----
    const int4 c0 = __ldg(reinterpret_cast<const int4*>(context + e * CTX));
    const int4 c1 = __ldg(reinterpret_cast<const int4*>(context + e * CTX) + 1);
    int cidx[CTX] = {c0.x, c0.y, c0.z, c0.w, c1.x, c1.y, c1.z, c1.w};

    // ---- v = mean of 8 context rows; lane holds slots {sub, sub+16} ----
    float4 v0, v1;
    {
        const float4* r = reinterpret_cast<const float4*>(
                              in_embed + (size_t)cidx[0] * D);
        v0 = __ldg(r + sub);
        v1 = __ldg(r + sub + 16);
    }
    #pragma unroll
    for (int c = 1; c < CTX; c++) {
        const float4* r = reinterpret_cast<const float4*>(
                              in_embed + (size_t)cidx[c] * D);
        const float4 a = __ldg(r + sub);
        const float4 b = __ldg(r + sub + 16);
        v0.x += a.x; v0.y += a.y; v0.z += a.z; v0.w += a.w;
        v1.x += b.x; v1.y += b.y; v1.z += b.z; v1.w += b.w;
    }
    const float inv = 1.0f / (float)CTX;
    v0.x *= inv; v0.y *= inv; v0.z *= inv; v0.w *= inv;
    v1.x *= inv; v1.y *= inv; v1.z *= inv; v1.w *= inv;

    // ---- u-row indices (vectorized; short liveness) ----
    int ridx[NEG + 1];
    ridx[0] = __ldg(&target[e]);
    {
        const int2 n01 = __ldg(reinterpret_cast<const int2*>(negatives + e * NEG));
        const int2 n23 = __ldg(reinterpret_cast<const int2*>(negatives + e * NEG) + 1);
        const int2 n45 = __ldg(reinterpret_cast<const int2*>(negatives + e * NEG) + 2);
        const int2 n67 = __ldg(reinterpret_cast<const int2*>(negatives + e * NEG) + 3);
        const int2 n89 = __ldg(reinterpret_cast<const int2*>(negatives + e * NEG) + 4);
        ridx[1] = n01.x; ridx[2]  = n01.y; ridx[3] = n23.x; ridx[4]  = n23.y;
        ridx[5] = n45.x; ridx[6]  = n45.y; ridx[7] = n67.x; ridx[8]  = n67.y;
        ridx[9] = n89.x; ridx[10] = n89.y;
    }

    // ---- 11 per-lane partial dots; out_embed loads get evict_last ----
    float s[NEG + 1];
    #pragma unroll
    for (int i = 0; i < NEG + 1; i++) {
        const float4* u = reinterpret_cast<const float4*>(
                              out_embed + (size_t)ridx[i] * D);
        const float4 a = ldg_keep(u + sub);
        const float4 b = ldg_keep(u + sub + 16);
        s[i] = dot4(v0, a) + dot4(v1, b);
    }

    // ---- reduce each score within the 16-lane group (4 stages) ----
    #pragma unroll
    for (int i = 0; i < NEG + 1; i++) {
        float x = s[i];
        x += __shfl_xor_sync(0xffffffffu, x, 8);
        x += __shfl_xor_sync(0xffffffffu, x, 4);
        x += __shfl_xor_sync(0xffffffffu, x, 2);
        x += __shfl_xor_sync(0xffffffffu, x, 1);
        s[i] = x;
    }

    // ---- epilogue: 2 group leaders per warp in parallel lanes ----
    if (sub == 0) {
        float acc = log_sigmoid_fast(s[0]);
        #pragma unroll
        for (int k = 0; k < NEG; k++)
            acc += log_sigmoid_fast(-s[1 + k]);
        out[e] = -acc;
    }
}

extern "C" void kernel_launch(void* const* d_in, const int* in_sizes, int n_in,
                              void* d_out, int out_size)
{
    const float* in_embed  = (const float*)d_in[0];
    const float* out_embed = (const float*)d_in[1];
    const int*   context   = (const int*)d_in[2];
    const int*   target    = (const int*)d_in[3];
    const int*   negatives = (const int*)d_in[4];
    float*       out       = (float*)d_out;

    const int B = out_size;                       // 16384
    const int warps = (B + 1) / 2;                // 2 elements per warp
    const int threads = 128;                      // 4 warps/block
    const int blocks = (warps * 32 + threads - 1) / threads;   // 2048
    cbow_neg_kernel<<<blocks, threads>>>(in_embed, out_embed, context, target,
                                         negatives, out, B);
}

// round 14
// speedup vs baseline: 1.2604x; 1.0174x over previous
#include <cuda_runtime.h>
#include <cstdint>
#include <math.h>

// CBOW negative-sampling loss.
//   d_in[0]: in_embed  float32 [100000, 128]
//   d_in[1]: out_embed float32 [100000, 128]
//   d_in[2]: context   int32   [B, 8]
//   d_in[3]: target    int32   [B]
//   d_in[4]: negatives int32   [B, 10]
// Output: float32 [B]
//
// Round 14: R5 structure (best: 18.46us — 2 elements/warp, 16-lane groups,
// 128-thread blocks) + bounded micro-tweaks at the measured service ceiling:
//   1) vectorized index loads (int4 x2 ctx, int2 x5 negs)
//   2) depth-2 software pipeline in the u-dot loop (load pair i+1 before
//      consuming pair i) -> >=2 u-row loads outstanding, +16 regs max
//   3) __launch_bounds__(128, 9): pin reg budget at 56 (~R5's natural 55)
//      while guaranteeing 9 CTAs/SM -> 36 warps/SM theoretical.
// Evidence base: random-512B gather service rate (~4TB/s DRAM, queues full)
// is the wall; cp.async/pipelining/L2-policy all proven non-levers (R9-13).

#define CTX 8
#define NEG 10
#define D   128

__device__ __forceinline__ float log_sigmoid_fast(float x) {
    return fminf(x, 0.0f) - __logf(1.0f + __expf(-fabsf(x)));
}

__device__ __forceinline__ float dot4(float4 a, float4 b) {
    return a.x * b.x + a.y * b.y + a.z * b.z + a.w * b.w;
}

__global__ __launch_bounds__(128, 9) void cbow_neg_kernel(
    const float* __restrict__ in_embed,
    const float* __restrict__ out_embed,
    const int*   __restrict__ context,
    const int*   __restrict__ target,
    const int*   __restrict__ negatives,
    float*       __restrict__ out,
    int B)
{
    const int lane   = threadIdx.x & 31;
    const int warpId = (blockIdx.x * blockDim.x + threadIdx.x) >> 5;
    const int group  = lane >> 4;            // 0..1: element within warp
    const int sub    = lane & 15;            // 0..15: lane within group
    const int e      = warpId * 2 + group;   // batch element
    if (e >= B) return;                      // B even, warp-uniform exit

    // ---- context indices (vectorized: 2x int4) ----
    const int4 c0 = __ldg(reinterpret_cast<const int4*>(context + e * CTX));
    const int4 c1 = __ldg(reinterpret_cast<const int4*>(context + e * CTX) + 1);
    const int cidx[CTX] = {c0.x, c0.y, c0.z, c0.w, c1.x, c1.y, c1.z, c1.w};

    // ---- v = mean of 8 context rows; lane holds slots {sub, sub+16} ----
    float4 v0, v1;
    {
        const float4* r = reinterpret_cast<const float4*>(
                              in_embed + (size_t)cidx[0] * D);
        v0 = __ldg(r + sub);
        v1 = __ldg(r + sub + 16);
    }
    #pragma unroll
    for (int c = 1; c < CTX; c++) {
        const float4* r = reinterpret_cast<const float4*>(
                              in_embed + (size_t)cidx[c] * D);
        const float4 a = __ldg(r + sub);
        const float4 b = __ldg(r + sub + 16);
        v0.x += a.x; v0.y += a.y; v0.z += a.z; v0.w += a.w;
        v1.x += b.x; v1.y += b.y; v1.z += b.z; v1.w += b.w;
    }
    const float inv = 1.0f / (float)CTX;
    v0.x *= inv; v0.y *= inv; v0.z *= inv; v0.w *= inv;
    v1.x *= inv; v1.y *= inv; v1.z *= inv; v1.w *= inv;

    // ---- u-row indices (vectorized; short liveness) ----
    int ridx[NEG + 1];
    ridx[0] = __ldg(&target[e]);
    {
        const int2* np = reinterpret_cast<const int2*>(negatives + e * NEG);
        const int2 n01 = __ldg(np);
        const int2 n23 = __ldg(np + 1);
        const int2 n45 = __ldg(np + 2);
        const int2 n67 = __ldg(np + 3);
        const int2 n89 = __ldg(np + 4);
        ridx[1] = n01.x; ridx[2]  = n01.y; ridx[3] = n23.x; ridx[4]  = n23.y;
        ridx[5] = n45.x; ridx[6]  = n45.y; ridx[7] = n67.x; ridx[8]  = n67.y;
        ridx[9] = n89.x; ridx[10] = n89.y;
    }

    // ---- 11 dots, depth-2 pipelined u-row loads ----
    float s[NEG + 1];
    {
        const float4* u0 = reinterpret_cast<const float4*>(
                               out_embed + (size_t)ridx[0] * D);
        float4 a = __ldg(u0 + sub);
        float4 b = __ldg(u0 + sub + 16);
        #pragma unroll
        for (int i = 0; i < NEG; i++) {
            const float4* un = reinterpret_cast<const float4*>(
                                   out_embed + (size_t)ridx[i + 1] * D);
            const float4 an = __ldg(un + sub);       // issue next pair
            const float4 bn = __ldg(un + sub + 16);  // before consuming current
            s[i] = dot4(v0, a) + dot4(v1, b);
            a = an; b = bn;
        }
        s[NEG] = dot4(v0, a) + dot4(v1, b);
    }

    // ---- reduce each score within the 16-lane group (4 stages) ----
    #pragma unroll
    for (int i = 0; i < NEG + 1; i++) {
        float x = s[i];
        x += __shfl_xor_sync(0xffffffffu, x, 8);
        x += __shfl_xor_sync(0xffffffffu, x, 4);
        x += __shfl_xor_sync(0xffffffffu, x, 2);
        x += __shfl_xor_sync(0xffffffffu, x, 1);
        s[i] = x;
    }

    // ---- epilogue: 2 group leaders per warp in parallel lanes ----
    if (sub == 0) {
        float acc = log_sigmoid_fast(s[0]);
        #pragma unroll
        for (int k = 0; k < NEG; k++)
            acc += log_sigmoid_fast(-s[1 + k]);
        out[e] = -acc;
    }
}

extern "C" void kernel_launch(void* const* d_in, const int* in_sizes, int n_in,
                              void* d_out, int out_size)
{
    const float* in_embed  = (const float*)d_in[0];
    const float* out_embed = (const float*)d_in[1];
    const int*   context   = (const int*)d_in[2];
    const int*   target    = (const int*)d_in[3];
    const int*   negatives = (const int*)d_in[4];
    float*       out       = (float*)d_out;

    const int B = out_size;                       // 16384
    const int warps = (B + 1) / 2;                // 2 elements per warp
    const int threads = 128;                      // 4 warps/block
    const int blocks = (warps * 32 + threads - 1) / threads;   // 2048
    cbow_neg_kernel<<<blocks, threads>>>(in_embed, out_embed, context, target,
                                         negatives, out, B);
}

// round 15
// speedup vs baseline: 1.3672x; 1.0847x over previous
#include <cuda_runtime.h>
#include <cstdint>
#include <math.h>

// CBOW negative-sampling loss.
//   d_in[0]: in_embed  float32 [100000, 128]
//   d_in[1]: out_embed float32 [100000, 128]
//   d_in[2]: context   int32   [B, 8]
//   d_in[3]: target    int32   [B]
//   d_in[4]: negatives int32   [B, 10]
// Output: float32 [B]
//
// Round 15: R14 (best: 18.43us) with ONE change — ctx-row loads use __ldcs
// (evict-first / streaming). Complement of R13's inert evict_last: instead
// of protecting out_embed, demote in_embed so default LRU keeps out_embed
// (51MB, 58% of row touches) resident across graph replays. Everything
// else byte-identical to R14 for single-variable attribution.
//
// Established model (R1-R14): random 512B row-gather service rate
// (~4TB/s DRAM-side, queues full) is the wall; reg-MLP sweeps, cp.async
// one-shot and double-buffered pipelines, and L2 protection policies all
// converge to it. R14 sits on the wall: 2 elem/warp, 16-lane groups,
// 128-thr blocks, regs pinned at 56 via __launch_bounds__(128, 9).

#define CTX 8
#define NEG 10
#define D   128

__device__ __forceinline__ float log_sigmoid_fast(float x) {
    return fminf(x, 0.0f) - __logf(1.0f + __expf(-fabsf(x)));
}

__device__ __forceinline__ float dot4(float4 a, float4 b) {
    return a.x * b.x + a.y * b.y + a.z * b.z + a.w * b.w;
}

__global__ __launch_bounds__(128, 9) void cbow_neg_kernel(
    const float* __restrict__ in_embed,
    const float* __restrict__ out_embed,
    const int*   __restrict__ context,
    const int*   __restrict__ target,
    const int*   __restrict__ negatives,
    float*       __restrict__ out,
    int B)
{
    const int lane   = threadIdx.x & 31;
    const int warpId = (blockIdx.x * blockDim.x + threadIdx.x) >> 5;
    const int group  = lane >> 4;            // 0..1: element within warp
    const int sub    = lane & 15;            // 0..15: lane within group
    const int e      = warpId * 2 + group;   // batch element
    if (e >= B) return;                      // B even, warp-uniform exit

    // ---- context indices (vectorized: 2x int4) ----
    const int4 c0 = __ldg(reinterpret_cast<const int4*>(context + e * CTX));
    const int4 c1 = __ldg(reinterpret_cast<const int4*>(context + e * CTX) + 1);
    const int cidx[CTX] = {c0.x, c0.y, c0.z, c0.w, c1.x, c1.y, c1.z, c1.w};

    // ---- v = mean of 8 context rows (STREAMING loads: evict-first) ----
    float4 v0, v1;
    {
        const float4* r = reinterpret_cast<const float4*>(
                              in_embed + (size_t)cidx[0] * D);
        v0 = __ldcs(r + sub);
        v1 = __ldcs(r + sub + 16);
    }
    #pragma unroll
    for (int c = 1; c < CTX; c++) {
        const float4* r = reinterpret_cast<const float4*>(
                              in_embed + (size_t)cidx[c] * D);
        const float4 a = __ldcs(r + sub);
        const float4 b = __ldcs(r + sub + 16);
        v0.x += a.x; v0.y += a.y; v0.z += a.z; v0.w += a.w;
        v1.x += b.x; v1.y += b.y; v1.z += b.z; v1.w += b.w;
    }
    const float inv = 1.0f / (float)CTX;
    v0.x *= inv; v0.y *= inv; v0.z *= inv; v0.w *= inv;
    v1.x *= inv; v1.y *= inv; v1.z *= inv; v1.w *= inv;

    // ---- u-row indices (vectorized; short liveness) ----
    int ridx[NEG + 1];
    ridx[0] = __ldg(&target[e]);
    {
        const int2* np = reinterpret_cast<const int2*>(negatives + e * NEG);
        const int2 n01 = __ldg(np);
        const int2 n23 = __ldg(np + 1);
        const int2 n45 = __ldg(np + 2);
        const int2 n67 = __ldg(np + 3);
        const int2 n89 = __ldg(np + 4);
        ridx[1] = n01.x; ridx[2]  = n01.y; ridx[3] = n23.x; ridx[4]  = n23.y;
        ridx[5] = n45.x; ridx[6]  = n45.y; ridx[7] = n67.x; ridx[8]  = n67.y;
        ridx[9] = n89.x; ridx[10] = n89.y;
    }

    // ---- 11 dots, depth-2 pipelined u-row loads (default caching) ----
    float s[NEG + 1];
    {
        const float4* u0 = reinterpret_cast<const float4*>(
                               out_embed + (size_t)ridx[0] * D);
        float4 a = __ldg(u0 + sub);
        float4 b = __ldg(u0 + sub + 16);
        #pragma unroll
        for (int i = 0; i < NEG; i++) {
            const float4* un = reinterpret_cast<const float4*>(
                                   out_embed + (size_t)ridx[i + 1] * D);
            const float4 an = __ldg(un + sub);       // issue next pair
            const float4 bn = __ldg(un + sub + 16);  // before consuming current
            s[i] = dot4(v0, a) + dot4(v1, b);
            a = an; b = bn;
        }
        s[NEG] = dot4(v0, a) + dot4(v1, b);
    }

    // ---- reduce each score within the 16-lane group (4 stages) ----
    #pragma unroll
    for (int i = 0; i < NEG + 1; i++) {
        float x = s[i];
        x += __shfl_xor_sync(0xffffffffu, x, 8);
        x += __shfl_xor_sync(0xffffffffu, x, 4);
        x += __shfl_xor_sync(0xffffffffu, x, 2);
        x += __shfl_xor_sync(0xffffffffu, x, 1);
        s[i] = x;
    }

    // ---- epilogue: 2 group leaders per warp in parallel lanes ----
    if (sub == 0) {
        float acc = log_sigmoid_fast(s[0]);
        #pragma unroll
        for (int k = 0; k < NEG; k++)
            acc += log_sigmoid_fast(-s[1 + k]);
        out[e] = -acc;
    }
}

extern "C" void kernel_launch(void* const* d_in, const int* in_sizes, int n_in,
                              void* d_out, int out_size)
{
    const float* in_embed  = (const float*)d_in[0];
    const float* out_embed = (const float*)d_in[1];
    const int*   context   = (const int*)d_in[2];
    const int*   target    = (const int*)d_in[3];
    const int*   negatives = (const int*)d_in[4];
    float*       out       = (float*)d_out;

    const int B = out_size;                       // 16384
    const int warps = (B + 1) / 2;                // 2 elements per warp
    const int threads = 128;                      // 4 warps/block
    const int blocks = (warps * 32 + threads - 1) / threads;   // 2048
    cbow_neg_kernel<<<blocks, threads>>>(in_embed, out_embed, context, target,
                                         negatives, out, B);
}